// round 16
// baseline (speedup 1.0000x reference)
#include <cuda_runtime.h>
#include <cuda_bf16.h>
#include <cstdint>

#define NCTA 128
#define NTHR 512
static constexpr int Bn = 32, Tn = 64, Sn = 128, Hn = 512, En = 512, Vn = 32000;
static constexpr float NEGV = -1e4f;

// ---------------- device scratch (allocation-free) ----------------
__device__ __align__(16) float g_x[Bn * Tn][En];
__device__ __align__(16) float g_xw[Bn * Tn * 2048];
__device__ __align__(16) float g_feedT[Hn][Bn];
__device__ __align__(16) float g_h0T[2][Hn][Bn];
__device__ __align__(16) float g_h1T[2][Hn][Bn];
__device__ __align__(16) float g_ctxT[Hn][Bn];
__device__ __align__(16) float g_encq[Bn * Sn][Hn];
__device__ __align__(16) float g_attT[Hn * Hn];
__device__ __align__(16) float g_wT[Hn * Hn];           // out_proj_w transposed
__device__ __align__(16) float g_bv[Vn];                // embed @ out_proj_b
__device__ __nv_bfloat16 g_Ahi[Bn * Tn * En];           // dec hi (b-major rows)
__device__ __nv_bfloat16 g_Alo[Bn * Tn * En];
__device__ __nv_bfloat16 g_Bhi[(size_t)Vn * En];        // embed hi
__device__ __nv_bfloat16 g_Blo[(size_t)Vn * En];
__device__ __nv_bfloat16 g_wThi[Hn * Hn];
__device__ __nv_bfloat16 g_wTlo[Hn * Hn];
__device__ __nv_bfloat16 g_Mhi[(size_t)Vn * En];        // M = embed @ out_proj_w (hi/lo)
__device__ __nv_bfloat16 g_Mlo[(size_t)Vn * En];
__device__ unsigned g_count;
__device__ volatile unsigned g_gen;

// ---------------- small helpers ----------------
__device__ __forceinline__ uint32_t s2u(const void* p)
{
    uint32_t a;
    asm("{ .reg .u64 t; cvta.to.shared.u64 t, %1; cvt.u32.u64 %0, t; }" : "=r"(a) : "l"(p));
    return a;
}
__device__ __forceinline__ void cp16(uint32_t s, const void* g)
{
    asm volatile("cp.async.cg.shared.global [%0], [%1], 16;" :: "r"(s), "l"(g) : "memory");
}
__device__ __forceinline__ float sigm(float x) { return 1.f / (1.f + __expf(-x)); }

__device__ __forceinline__ unsigned long long pack2(float x)
{ unsigned long long r; asm("mov.b64 %0, {%1, %1};" : "=l"(r) : "f"(x)); return r; }
__device__ __forceinline__ unsigned long long pack2f(float x, float y)
{ unsigned long long r; asm("mov.b64 %0, {%1, %2};" : "=l"(r) : "f"(x), "f"(y)); return r; }
__device__ __forceinline__ void ffma2(unsigned long long& d, unsigned long long a, unsigned long long b)
{ asm("fma.rn.f32x2 %0, %1, %2, %0;" : "+l"(d) : "l"(a), "l"(b)); }
__device__ __forceinline__ float2 unpack2(unsigned long long v)
{ float2 r; asm("mov.b64 {%0, %1}, %2;" : "=f"(r.x), "=f"(r.y) : "l"(v)); return r; }

__device__ __forceinline__ void split_bf16(float v, __nv_bfloat16& h, __nv_bfloat16& l)
{
    h = __float2bfloat16(v);
    l = __float2bfloat16(v - __bfloat162float(h));
}

// ---------------- grid barrier (128 CTAs co-resident) ----------------
__device__ __forceinline__ void gbar()
{
    __threadfence();
    __syncthreads();
    if (threadIdx.x == 0) {
        unsigned g = g_gen;
        unsigned a = atomicAdd(&g_count, 1u);
        if (a == NCTA - 1u) {
            g_count = 0u;
            __threadfence();
            g_gen = g + 1u;
        } else {
            while (g_gen == g) { }
        }
    }
    __syncthreads();
    __threadfence();
}

// dynamic smem for recurrent: packed f32x2 weights [warp][kpair][row]
static constexpr int WA2 = 8192, WB2 = 8192, WE2 = 2048;
static constexpr int DSMEM = (WA2 + WB2 + WE2) * 8;   // 147456 B

// ---------------- embed gather ----------------
__global__ void __launch_bounds__(256)
gather_x(const int* __restrict__ tokens, const float* __restrict__ embed)
{
    int p = blockIdx.x * 8 + (threadIdx.x >> 5);
    int lane = threadIdx.x & 31;
    int t = p >> 5, b = p & 31;
    int tok = __ldg(tokens + b * Tn + t);
    const float4* er = (const float4*)(embed + (size_t)tok * En);
    float4* dr = (float4*)g_x[t * Bn + b];
#pragma unroll
    for (int i = 0; i < 4; i++)
        dr[i * 32 + lane] = __ldg(er + i * 32 + lane);
}

// warp-sliced matvec over one 64-k slice
template<int NR>
__device__ __forceinline__ void mv16(const float2* __restrict__ wslice,
                                     const float* __restrict__ act,
                                     int lane, float* __restrict__ red)
{
    unsigned long long acc[NR];
#pragma unroll
    for (int r = 0; r < NR; r++) acc[r] = 0ull;
#pragma unroll 8
    for (int kp = 0; kp < 32; kp++) {
        float a0 = __ldca(act + kp * 64 + lane);
        float a1 = __ldca(act + kp * 64 + 32 + lane);
        unsigned long long av = pack2f(a0, a1);
        const ulonglong2* wrow = (const ulonglong2*)(wslice + kp * NR);
#pragma unroll
        for (int rp = 0; rp < NR / 2; rp++) {
            ulonglong2 wv = wrow[rp];
            ffma2(acc[rp * 2], wv.x, av);
            ffma2(acc[rp * 2 + 1], wv.y, av);
        }
    }
#pragma unroll
    for (int r = 0; r < NR; r++) {
        float2 v = unpack2(acc[r]);
        red[r * 32 + lane] = v.x + v.y;
    }
}

// ---------------- persistent recurrence (512 threads: 16 warps) ----------------
__global__ void __launch_bounds__(NTHR, 1)
recurrent_kernel(const float* __restrict__ enc,
                 const int* __restrict__ mask,
                 const float* __restrict__ w_ih0, const float* __restrict__ w_hh0,
                 const float* __restrict__ b_ih0, const float* __restrict__ b_hh0,
                 const float* __restrict__ w_ih1, const float* __restrict__ w_hh1,
                 const float* __restrict__ b_ih1, const float* __restrict__ b_hh1,
                 const float* __restrict__ attn_out_w)
{
    extern __shared__ __align__(16) float2 wsm2[];
    float2* wA = wsm2;
    float2* wB = wA + WA2;
    float2* wE = wB + WB2;

    const int tid = threadIdx.x, cta = blockIdx.x;
    const int warp = tid >> 5, lane = tid & 31;
    const int gtid = cta * NTHR + tid;

    __shared__ __align__(16) float sAred[16][16][32];
    __shared__ __align__(16) float gs[16][32];
    __shared__ __align__(16) float s_q[512];
    __shared__ float s_sc[128];
    __shared__ float s_red[32];

    for (int i = gtid; i < Hn * Bn; i += NCTA * NTHR) {
        (&g_feedT[0][0])[i] = 0.f;
        (&g_h0T[0][0][0])[i] = 0.f; (&g_h0T[1][0][0])[i] = 0.f;
        (&g_h1T[0][0][0])[i] = 0.f; (&g_h1T[1][0][0])[i] = 0.f;
    }

    // stage packed weights
    for (int i = tid; i < WA2; i += NTHR) {
        int w = i >> 9, kp = (i >> 4) & 31, r = i & 15;
        int grow = (r & 3) * 512 + cta * 4 + (r >> 2);
        int k = w * 64 + kp * 2;
        float2 v;
        if (k < 512) {
            const float* p = w_ih0 + (size_t)grow * 1024 + 512 + k;
            v = make_float2(__ldg(p), __ldg(p + 1));
        } else {
            const float* p = w_hh0 + (size_t)grow * 512 + (k - 512);
            v = make_float2(__ldg(p), __ldg(p + 1));
        }
        wA[i] = v;
    }
    for (int i = tid; i < WB2; i += NTHR) {
        int w = i >> 9, kp = (i >> 4) & 31, r = i & 15;
        int grow = (r & 3) * 512 + cta * 4 + (r >> 2);
        int k = w * 64 + kp * 2;
        float2 v;
        if (k < 512) {
            const float* p = w_ih1 + (size_t)grow * 512 + k;
            v = make_float2(__ldg(p), __ldg(p + 1));
        } else {
            const float* p = w_hh1 + (size_t)grow * 512 + (k - 512);
            v = make_float2(__ldg(p), __ldg(p + 1));
        }
        wB[i] = v;
    }
    for (int i = tid; i < WE2; i += NTHR) {
        int w = i >> 7, kp = (i >> 2) & 31, r = i & 3;
        int k = w * 64 + kp * 2;
        const float* p = attn_out_w + (size_t)(cta * 4 + r) * 1024 + k;
        wE[i] = make_float2(__ldg(p), __ldg(p + 1));
    }
    gbar();

    const int db = cta >> 2, dp = cta & 3;
    const int dh = dp * 128 + (tid & 127);
    const int dslice = tid >> 7;

    float c0r = 0.f, c1r = 0.f;
    float biA[4], biB[4];
    if (tid < 128) {
        int jj = tid >> 5, ju = cta * 4 + jj;
#pragma unroll
        for (int rr = 0; rr < 4; rr++) {
            biA[rr] = __ldg(b_ih0 + ju + 512 * rr) + __ldg(b_hh0 + ju + 512 * rr);
            biB[rr] = __ldg(b_ih1 + ju + 512 * rr) + __ldg(b_hh1 + ju + 512 * rr);
        }
    }

    for (int t = 0; t < Tn; t++) {
        const int cur = t & 1, prv = cur ^ 1;

        // ---------- Phase A ----------
        {
            float xwv[4];
            if (tid < 128) {
                int b = tid & 31, jj = tid >> 5;
                const float* xwrow = g_xw + (size_t)(t * Bn + b) * 2048 + cta * 4 + jj;
#pragma unroll
                for (int rr = 0; rr < 4; rr++) xwv[rr] = __ldcg(xwrow + 512 * rr);
            }
            const float* act = (warp < 8) ? &g_feedT[warp * 64][0]
                                          : &g_h0T[prv][(warp - 8) * 64][0];
            mv16<16>(wA + warp * 32 * 16, act, lane, &sAred[warp][0][0]);
            __syncthreads();
            {
                int row = tid >> 5, b = tid & 31;
                float s = 0.f;
#pragma unroll
                for (int w = 0; w < 16; w++) s += sAred[w][row][b];
                gs[row][b] = s;
            }
            __syncthreads();
            if (tid < 128) {
                int b = tid & 31, jj = tid >> 5;
                float gi = gs[jj * 4 + 0][b] + biA[0] + xwv[0];
                float gf = gs[jj * 4 + 1][b] + biA[1] + xwv[1];
                float gg = gs[jj * 4 + 2][b] + biA[2] + xwv[2];
                float go = gs[jj * 4 + 3][b] + biA[3] + xwv[3];
                c0r = sigm(gf) * c0r + sigm(gi) * tanhf(gg);
                g_h0T[cur][cta * 4 + jj][b] = sigm(go) * tanhf(c0r);
            }
        }
        gbar();

        // ---------- Phase B ----------
        {
            const float* act = (warp < 8) ? &g_h0T[cur][warp * 64][0]
                                          : &g_h1T[prv][(warp - 8) * 64][0];
            mv16<16>(wB + warp * 32 * 16, act, lane, &sAred[warp][0][0]);
            __syncthreads();
            {
                int row = tid >> 5, b = tid & 31;
                float s = 0.f;
#pragma unroll
                for (int w = 0; w < 16; w++) s += sAred[w][row][b];
                gs[row][b] = s;
            }
            __syncthreads();
            if (tid < 128) {
                int b = tid & 31, jj = tid >> 5;
                float gi = gs[jj * 4 + 0][b] + biB[0];
                float gf = gs[jj * 4 + 1][b] + biB[1];
                float gg = gs[jj * 4 + 2][b] + biB[2];
                float go = gs[jj * 4 + 3][b] + biB[3];
                c1r = sigm(gf) * c1r + sigm(gi) * tanhf(gg);
                g_h1T[cur][cta * 4 + jj][b] = sigm(go) * tanhf(c1r);
            }
        }
        gbar();

        // ---------- Phase D ----------
        {
            const int b = db;
            s_q[tid] = __ldca(&g_h1T[cur][tid][b]);
            __syncthreads();
#pragma unroll
            for (int i = 0; i < 8; i++) {
                int sp = warp * 8 + i;
                const float4* er = (const float4*)(g_encq[(size_t)b * Sn + sp]);
                const float4* qr = (const float4*)s_q;
                float acc = 0.f;
#pragma unroll
                for (int c4 = 0; c4 < 4; c4++) {
                    float4 e = __ldca(er + c4 * 32 + lane);
                    float4 q4 = qr[c4 * 32 + lane];
                    acc += e.x * q4.x + e.y * q4.y + e.z * q4.z + e.w * q4.w;
                }
#pragma unroll
                for (int o = 16; o; o >>= 1) acc += __shfl_xor_sync(~0u, acc, o);
                if (lane == 0)
                    s_sc[sp] = (__ldg(mask + b * Sn + sp) == 0) ? NEGV : acc;
            }
            __syncthreads();
            float mv = (tid < 128) ? s_sc[tid] : -3e38f;
#pragma unroll
            for (int o = 16; o; o >>= 1) mv = fmaxf(mv, __shfl_xor_sync(~0u, mv, o));
            if (tid < 128 && lane == 0) s_red[warp] = mv;
            __syncthreads();
            if (tid == 0) {
                float m = s_red[0];
                for (int w = 1; w < 4; w++) m = fmaxf(m, s_red[w]);
                s_red[16] = m;
            }
            __syncthreads();
            float ev = 0.f;
            if (tid < 128) ev = __expf(s_sc[tid] - s_red[16]);
            float sv = ev;
#pragma unroll
            for (int o = 16; o; o >>= 1) sv += __shfl_xor_sync(~0u, sv, o);
            if (tid < 128 && lane == 0) s_red[warp] = sv;
            __syncthreads();
            if (tid == 0) {
                float s = 0.f;
                for (int w = 0; w < 4; w++) s += s_red[w];
                s_red[17] = 1.f / s;
            }
            __syncthreads();
            if (tid < 128) s_sc[tid] = ev * s_red[17];
            __syncthreads();
            {
                const int s0 = dslice * 32;
                const float* ep = enc + (size_t)b * Sn * Hn + dh;
                float a[8];
#pragma unroll
                for (int st = 0; st < 8; st++) a[st] = 0.f;
#pragma unroll
                for (int jj2 = 0; jj2 < 4; jj2++)
#pragma unroll
                    for (int st = 0; st < 8; st++) {
                        int s = s0 + st * 4 + jj2;
                        a[st] += s_sc[s] * __ldg(ep + (size_t)s * Hn);
                    }
                float sum = ((a[0] + a[1]) + (a[2] + a[3])) + ((a[4] + a[5]) + (a[6] + a[7]));
                ((float*)sAred)[dslice * 128 + (tid & 127)] = sum;
            }
            __syncthreads();
            if (tid < 128) {
                float* pp = (float*)sAred;
                g_ctxT[dp * 128 + tid][db] = (pp[tid] + pp[128 + tid]) + (pp[256 + tid] + pp[384 + tid]);
            }
        }
        gbar();

        // ---------- Phase E: feed = tanh(...); dec written directly as bf16 hi/lo ----------
        {
            const float* act = (warp < 8) ? &g_ctxT[warp * 64][0]
                                          : &g_h1T[cur][(warp - 8) * 64][0];
            mv16<4>(wE + warp * 32 * 4, act, lane, &sAred[warp][0][0]);
            __syncthreads();
            if (tid < 128) {
                int b = tid & 31, row = tid >> 5;
                float s = 0.f;
#pragma unroll
                for (int w = 0; w < 16; w++) s += sAred[w][row][b];
                float f = tanhf(s);
                g_feedT[cta * 4 + row][b] = f;
                __nv_bfloat16 h, l;
                split_bf16(f, h, l);
                size_t off = (size_t)(b * Tn + t) * En + cta * 4 + row;
                g_Ahi[off] = h;
                g_Alo[off] = l;
            }
        }
        gbar();
    }
}

// ---------------- 512x512 transpose ----------------
__global__ void __launch_bounds__(256)
trans512(const float* __restrict__ src, float* __restrict__ dst)
{
    __shared__ float tile[32][33];
    int bx = blockIdx.x * 32, by = blockIdx.y * 32;
    int tx = threadIdx.x & 31, ty = threadIdx.x >> 5;
#pragma unroll
    for (int i = 0; i < 4; i++)
        tile[ty + i * 8][tx] = __ldg(src + (size_t)(by + ty + i * 8) * 512 + bx + tx);
    __syncthreads();
#pragma unroll
    for (int i = 0; i < 4; i++)
        dst[(size_t)(bx + ty + i * 8) * 512 + by + tx] = tile[tx][ty + i * 8];
}

// ---------------- SIMT f32x2 gemm: C = A @ W^T, fp32; W row stride ldw ----------------
__global__ void __launch_bounds__(256)
gemm_nt(const float* __restrict__ A, const float* __restrict__ W,
        const float* __restrict__ bias, float* __restrict__ C,
        int M, int N, int K, int ldw)
{
    __shared__ __align__(16) float As[16][128];
    __shared__ __align__(16) float Ws[16][128];
    const int m0 = blockIdx.y * 128, n0 = blockIdx.x * 128;
    const int tid = threadIdx.x;
    const int tx = tid & 15, ty = tid >> 4;
    const int lrow = tid >> 1, lcol = (tid & 1) * 8;

    unsigned long long acc2[8][4];
#pragma unroll
    for (int i = 0; i < 8; i++)
#pragma unroll
        for (int jj = 0; jj < 4; jj++) acc2[i][jj] = 0ull;

    const float* Aload = A + (size_t)(m0 + lrow) * K + lcol;
    const float* Wload = W + (size_t)(n0 + lrow) * ldw + lcol;

    for (int k0 = 0; k0 < K; k0 += 16) {
        float4 a0 = __ldg((const float4*)(Aload + k0));
        float4 a1 = __ldg((const float4*)(Aload + k0 + 4));
        float4 w0 = __ldg((const float4*)(Wload + k0));
        float4 w1 = __ldg((const float4*)(Wload + k0 + 4));
        __syncthreads();
        As[lcol + 0][lrow] = a0.x; As[lcol + 1][lrow] = a0.y;
        As[lcol + 2][lrow] = a0.z; As[lcol + 3][lrow] = a0.w;
        As[lcol + 4][lrow] = a1.x; As[lcol + 5][lrow] = a1.y;
        As[lcol + 6][lrow] = a1.z; As[lcol + 7][lrow] = a1.w;
        Ws[lcol + 0][lrow] = w0.x; Ws[lcol + 1][lrow] = w0.y;
        Ws[lcol + 2][lrow] = w0.z; Ws[lcol + 3][lrow] = w0.w;
        Ws[lcol + 4][lrow] = w1.x; Ws[lcol + 5][lrow] = w1.y;
        Ws[lcol + 6][lrow] = w1.z; Ws[lcol + 7][lrow] = w1.w;
        __syncthreads();
#pragma unroll
        for (int kk = 0; kk < 16; kk++) {
            float4 av0 = *(const float4*)&As[kk][ty * 8];
            float4 av1 = *(const float4*)&As[kk][ty * 8 + 4];
            const ulonglong2* wp = (const ulonglong2*)&Ws[kk][tx * 8];
            ulonglong2 b01 = wp[0], b23 = wp[1];
            float a8[8] = {av0.x, av0.y, av0.z, av0.w, av1.x, av1.y, av1.z, av1.w};
#pragma unroll
            for (int i = 0; i < 8; i++) {
                unsigned long long a2 = pack2(a8[i]);
                ffma2(acc2[i][0], a2, b01.x);
                ffma2(acc2[i][1], a2, b01.y);
                ffma2(acc2[i][2], a2, b23.x);
                ffma2(acc2[i][3], a2, b23.y);
            }
        }
    }
#pragma unroll
    for (int i = 0; i < 8; i++) {
        float* Crow = C + (size_t)(m0 + ty * 8 + i) * N + n0 + tx * 8;
#pragma unroll
        for (int jj = 0; jj < 4; jj++) {
            float2 v = unpack2(acc2[i][jj]);
            if (bias) {
                v.x += __ldg(bias + n0 + tx * 8 + 2 * jj);
                v.y += __ldg(bias + n0 + tx * 8 + 2 * jj + 1);
            }
            *(float2*)(Crow + 2 * jj) = v;
        }
    }
}

// ---------------- fp32 -> bf16 hi/lo split ----------------
__global__ void __launch_bounds__(256)
conv_split(const float4* __restrict__ src, uint2* __restrict__ hi, uint2* __restrict__ lo)
{
    int i = blockIdx.x * 256 + threadIdx.x;
    float4 v = __ldg(src + i);
    __nv_bfloat16 h0, l0, h1, l1, h2, l2, h3, l3;
    split_bf16(v.x, h0, l0); split_bf16(v.y, h1, l1);
    split_bf16(v.z, h2, l2); split_bf16(v.w, h3, l3);
    uint2 H, L;
    H.x = (uint32_t)__bfloat16_as_ushort(h0) | ((uint32_t)__bfloat16_as_ushort(h1) << 16);
    H.y = (uint32_t)__bfloat16_as_ushort(h2) | ((uint32_t)__bfloat16_as_ushort(h3) << 16);
    L.x = (uint32_t)__bfloat16_as_ushort(l0) | ((uint32_t)__bfloat16_as_ushort(l1) << 16);
    L.y = (uint32_t)__bfloat16_as_ushort(l2) | ((uint32_t)__bfloat16_as_ushort(l3) << 16);
    hi[i] = H; lo[i] = L;
}

// ---------------- bias vector: bv[v] = embed[v,:] . out_proj_b ----------------
__global__ void __launch_bounds__(256)
gemv_bias(const float* __restrict__ embed, const float* __restrict__ b)
{
    int v = blockIdx.x * 256 + threadIdx.x;
    const float4* er = (const float4*)(embed + (size_t)v * En);
    float acc = 0.f;
#pragma unroll 8
    for (int i = 0; i < 128; i++) {
        float4 e = __ldg(er + i);
        float4 bb = __ldg((const float4*)b + i);
        acc += e.x * bb.x + e.y * bb.y + e.z * bb.z + e.w * bb.w;
    }
    g_bv[v] = acc;
}

// ---------------- mma.sync bf16 3-pass GEMM core ----------------
static constexpr int KC = 32;
static constexpr int NCHUNK = En / KC;
static constexpr int ROWB = 80;
static constexpr int MATB = 128 * ROWB;
static constexpr int STAGEB = 4 * MATB;
static constexpr int GSMEM2 = 2 * STAGEB;

__device__ __forceinline__ void ldmA(uint32_t* r, uint32_t addr)
{
    asm volatile("ldmatrix.sync.aligned.m8n8.x4.shared.b16 {%0,%1,%2,%3}, [%4];"
                 : "=r"(r[0]), "=r"(r[1]), "=r"(r[2]), "=r"(r[3]) : "r"(addr));
}
__device__ __forceinline__ void ldmB(uint32_t* r, uint32_t addr)
{
    asm volatile("ldmatrix.sync.aligned.m8n8.x2.shared.b16 {%0,%1}, [%2];"
                 : "=r"(r[0]), "=r"(r[1]) : "r"(addr));
}
__device__ __forceinline__ void mma16816(float* d, const uint32_t* a, const uint32_t* b)
{
    asm volatile("mma.sync.aligned.m16n8k16.row.col.f32.bf16.bf16.f32 "
                 "{%0,%1,%2,%3}, {%4,%5,%6,%7}, {%8,%9}, {%0,%1,%2,%3};"
                 : "+f"(d[0]), "+f"(d[1]), "+f"(d[2]), "+f"(d[3])
                 : "r"(a[0]), "r"(a[1]), "r"(a[2]), "r"(a[3]), "r"(b[0]), "r"(b[1]));
}

// Shared tile routine: C_tile(m0,n0) of A @ B^T.
// SPLIT=false: write fp32 C (+bv). SPLIT=true: write bf16 hi/lo pair (Chi/Clo).
template<bool SPLIT>
__device__ void gemm_tile(char* smem,
                          const __nv_bfloat16* __restrict__ Ahi, const __nv_bfloat16* __restrict__ Alo,
                          const __nv_bfloat16* __restrict__ Bhi, const __nv_bfloat16* __restrict__ Blo,
                          const float* __restrict__ bv, float* __restrict__ C,
                          __nv_bfloat16* __restrict__ Chi, __nv_bfloat16* __restrict__ Clo,
                          int m0, int n0, int N, int K)
{
    const uint32_t su = s2u(smem);
    const int tid = threadIdx.x, wid = tid >> 5, lane = tid & 31;
    const int wm = wid & 1, wn = wid >> 1;

    auto load_stage = [&](int chunk) {
        const uint32_t sb = su + (chunk & 1) * STAGEB;
#pragma unroll
        for (int r8 = 0; r8 < 8; r8++) {
            int ci = tid + r8 * 256;
            int mat = ci >> 9, rem = ci & 511;
            int row = rem >> 2, seg = rem & 3;
            const __nv_bfloat16* g;
            if (mat == 0)      g = Ahi + (size_t)(m0 + row) * K + chunk * KC + seg * 8;
            else if (mat == 1) g = Alo + (size_t)(m0 + row) * K + chunk * KC + seg * 8;
            else if (mat == 2) g = Bhi + (size_t)(n0 + row) * K + chunk * KC + seg * 8;
            else               g = Blo + (size_t)(n0 + row) * K + chunk * KC + seg * 8;
            cp16(sb + mat * MATB + row * ROWB + seg * 16, g);
        }
        asm volatile("cp.async.commit_group;" ::: "memory");
    };

    float acc[4][4][4];
#pragma unroll
    for (int i = 0; i < 4; i++)
#pragma unroll
        for (int jj = 0; jj < 4; jj++)
#pragma unroll
            for (int k = 0; k < 4; k++) acc[i][jj][k] = 0.f;

    load_stage(0);
    load_stage(1);

    for (int c = 0; c < NCHUNK; c++) {
        if (c < NCHUNK - 1) asm volatile("cp.async.wait_group 1;" ::: "memory");
        else                asm volatile("cp.async.wait_group 0;" ::: "memory");
        __syncthreads();
        const uint32_t sb = su + (c & 1) * STAGEB;
        const uint32_t aHiB = sb,            aLoB = sb + MATB;
        const uint32_t bHiB = sb + 2 * MATB, bLoB = sb + 3 * MATB;
#pragma unroll
        for (int ks = 0; ks < 2; ks++) {
            const uint32_t aoff = (uint32_t)((wm * 64 + (lane & 15)) * ROWB
                                             + (ks * 16 + (lane >> 4) * 8) * 2);
            const int l = lane & 15;
            const uint32_t boff = (uint32_t)((wn * 32 + (l & 7)) * ROWB
                                             + (ks * 16 + (l >> 3) * 8) * 2);
            uint32_t ah[4][4], al[4][4], bh[4][2], bl[4][2];
#pragma unroll
            for (int mi = 0; mi < 4; mi++) {
                ldmA(ah[mi], aHiB + aoff + mi * 16 * ROWB);
                ldmA(al[mi], aLoB + aoff + mi * 16 * ROWB);
            }
#pragma unroll
            for (int ni = 0; ni < 4; ni++) {
                ldmB(bh[ni], bHiB + boff + ni * 8 * ROWB);
                ldmB(bl[ni], bLoB + boff + ni * 8 * ROWB);
            }
#pragma unroll
            for (int mi = 0; mi < 4; mi++)
#pragma unroll
                for (int ni = 0; ni < 4; ni++) {
                    mma16816(acc[mi][ni], ah[mi], bh[ni]);
                    mma16816(acc[mi][ni], ah[mi], bl[ni]);
                    mma16816(acc[mi][ni], al[mi], bh[ni]);
                }
        }
        __syncthreads();
        if (c + 2 < NCHUNK) load_stage(c + 2);
    }

    const int mbase = m0 + wm * 64 + (lane >> 2);
    const int nbase = n0 + wn * 32 + (lane & 3) * 2;
#pragma unroll
    for (int ni = 0; ni < 4; ni++) {
        float bv0 = 0.f, bv1 = 0.f;
        if (!SPLIT && bv) {
            bv0 = __ldg(bv + nbase + ni * 8);
            bv1 = __ldg(bv + nbase + ni * 8 + 1);
        }
#pragma unroll
        for (int mi = 0; mi < 4; mi++) {
#pragma unroll
            for (int half = 0; half < 2; half++) {
                int rm = mbase + mi * 16 + half * 8;
                float v0 = acc[mi][ni][half * 2], v1 = acc[mi][ni][half * 2 + 1];
                if (SPLIT) {
                    __nv_bfloat16 h0, l0, h1, l1;
                    split_bf16(v0, h0, l0);
                    split_bf16(v1, h1, l1);
                    size_t off = (size_t)rm * N + nbase + ni * 8;
                    uint32_t Hp = (uint32_t)__bfloat16_as_ushort(h0)
                                | ((uint32_t)__bfloat16_as_ushort(h1) << 16);
                    uint32_t Lp = (uint32_t)__bfloat16_as_ushort(l0)
                                | ((uint32_t)__bfloat16_as_ushort(l1) << 16);
                    *(uint32_t*)(Chi + off) = Hp;
                    *(uint32_t*)(Clo + off) = Lp;
                } else {
                    float* p = C + (size_t)rm * N + nbase + ni * 8;
                    *(float2*)p = make_float2(v0 + bv0, v1 + bv1);
                }
            }
        }
    }
}

// M-GEMM: Mhi/Mlo = split(embed_bf16 @ wT_bf16^T) — fused split epilogue
__global__ void __launch_bounds__(256, 2)
gemm_M(const __nv_bfloat16* __restrict__ Ahi, const __nv_bfloat16* __restrict__ Alo,
       const __nv_bfloat16* __restrict__ Bhi, const __nv_bfloat16* __restrict__ Blo)
{
    extern __shared__ char smem[];
    gemm_tile<true>(smem, Ahi, Alo, Bhi, Blo, nullptr, nullptr, g_Mhi, g_Mlo,
                    blockIdx.x * 128, blockIdx.y * 128, Hn, En);
}

// vocab GEMM: out = dec_bf16 @ M^T + bv
__global__ void __launch_bounds__(256, 2)
gemm_vocab(float* __restrict__ out)
{
    extern __shared__ char smem[];
    gemm_tile<false>(smem, g_Ahi, g_Alo, g_Mhi, g_Mlo, g_bv, out, nullptr, nullptr,
                     blockIdx.y * 128, blockIdx.x * 128, Vn, En);
}

extern "C" void kernel_launch(void* const* d_in, const int* in_sizes, int n_in,
                              void* d_out, int out_size)
{
    const int*   tokens     = (const int*)d_in[0];
    const float* enc        = (const float*)d_in[1];
    const int*   mask       = (const int*)d_in[2];
    const float* embed      = (const float*)d_in[3];
    const float* w_ih0      = (const float*)d_in[4];
    const float* w_hh0      = (const float*)d_in[5];
    const float* b_ih0      = (const float*)d_in[6];
    const float* b_hh0      = (const float*)d_in[7];
    const float* w_ih1      = (const float*)d_in[8];
    const float* w_hh1      = (const float*)d_in[9];
    const float* b_ih1      = (const float*)d_in[10];
    const float* b_hh1      = (const float*)d_in[11];
    const float* attn_in_w  = (const float*)d_in[12];
    const float* attn_out_w = (const float*)d_in[13];
    const float* out_proj_w = (const float*)d_in[14];
    const float* out_proj_b = (const float*)d_in[15];
    float* out = (float*)d_out;

    float *encq, *attT, *xrow, *xw, *wT;
    __nv_bfloat16 *Bhi, *Blo, *wThi, *wTlo;
    cudaGetSymbolAddress((void**)&encq, g_encq);
    cudaGetSymbolAddress((void**)&attT, g_attT);
    cudaGetSymbolAddress((void**)&xrow, g_x);
    cudaGetSymbolAddress((void**)&xw, g_xw);
    cudaGetSymbolAddress((void**)&wT, g_wT);
    cudaGetSymbolAddress((void**)&Bhi, g_Bhi);
    cudaGetSymbolAddress((void**)&Blo, g_Blo);
    cudaGetSymbolAddress((void**)&wThi, g_wThi);
    cudaGetSymbolAddress((void**)&wTlo, g_wTlo);

    cudaFuncSetAttribute(gemm_M, cudaFuncAttributeMaxDynamicSharedMemorySize, GSMEM2);
    cudaFuncSetAttribute(gemm_vocab, cudaFuncAttributeMaxDynamicSharedMemorySize, GSMEM2);
    cudaFuncSetAttribute(recurrent_kernel, cudaFuncAttributeMaxDynamicSharedMemorySize, DSMEM);

    static cudaStream_t s2 = nullptr, s3 = nullptr;
    static cudaEvent_t evA = nullptr, evM = nullptr, evX = nullptr;
    if (!s2) {
        cudaStreamCreateWithFlags(&s2, cudaStreamNonBlocking);
        cudaStreamCreateWithFlags(&s3, cudaStreamNonBlocking);
        cudaEventCreateWithFlags(&evA, cudaEventDisableTiming);
        cudaEventCreateWithFlags(&evM, cudaEventDisableTiming);
        cudaEventCreateWithFlags(&evX, cudaEventDisableTiming);
    }

    cudaEventRecord(evA, 0);
    cudaStreamWaitEvent(s2, evA, 0);
    cudaStreamWaitEvent(s3, evA, 0);

    // s2: M-chain — embed split, M = split(embed @ out_proj_w) fused, bias vec
    // (~200 us; mostly hidden under stream0 pre-GEMMs + early recurrence)
    conv_split<<<Vn * En / 1024, 256, 0, s2>>>((const float4*)embed, (uint2*)Bhi, (uint2*)Blo);
    trans512<<<dim3(16, 16), 256, 0, s2>>>(out_proj_w, wT);
    conv_split<<<Hn * Hn / 1024, 256, 0, s2>>>((const float4*)wT, (uint2*)wThi, (uint2*)wTlo);
    gemm_M<<<dim3(Vn / 128, Hn / 128), 256, GSMEM2, s2>>>(Bhi, Blo, wThi, wTlo);
    gemv_bias<<<Vn / 256, 256, 0, s2>>>(embed, out_proj_b);
    cudaEventRecord(evM, s2);

    // s3: x-side chain (xw precompute)
    gather_x<<<256, 256, 0, s3>>>(tokens, embed);
    gemm_nt<<<dim3(2048 / 128, (Bn * Tn) / 128), 256, 0, s3>>>(xrow, w_ih0, nullptr, xw,
                                                               Bn * Tn, 2048, 512, 1024);
    cudaEventRecord(evX, s3);

    // stream0: attn pre + recurrence + vocab GEMM
    trans512<<<dim3(16, 16), 256>>>(attn_in_w, attT);
    gemm_nt<<<dim3(Hn / 128, (Bn * Sn) / 128), 256>>>(enc, attT, nullptr, encq,
                                                      Bn * Sn, Hn, Hn, Hn);
    cudaStreamWaitEvent(0, evX, 0);
    recurrent_kernel<<<NCTA, NTHR, DSMEM>>>(enc, mask,
                                            w_ih0, w_hh0, b_ih0, b_hh0,
                                            w_ih1, w_hh1, b_ih1, b_hh1,
                                            attn_out_w);
    cudaStreamWaitEvent(0, evM, 0);
    gemm_vocab<<<dim3(Vn / 128, (Bn * Tn) / 128), 256, GSMEM2>>>(out);
}

// round 17
// speedup vs baseline: 1.0138x; 1.0138x over previous
#include <cuda_runtime.h>
#include <cuda_bf16.h>
#include <cstdint>

#define NCTA 128
#define NTHR 512
static constexpr int Bn = 32, Tn = 64, Sn = 128, Hn = 512, En = 512, Vn = 32000;
static constexpr float NEGV = -1e4f;

// ---------------- device scratch (allocation-free) ----------------
__device__ __align__(16) float g_x[Bn * Tn][En];
__device__ __align__(16) float g_xw[Bn * Tn * 2048];
__device__ __align__(16) float g_feedT[Hn][Bn];
__device__ __align__(16) float g_h0T[2][Hn][Bn];
__device__ __align__(16) float g_h1T[2][Hn][Bn];
__device__ __align__(16) float g_dec[Bn * Tn][Hn];
__device__ __align__(16) float g_encq[Bn * Sn][Hn];      // enc @ attn_in_w
__device__ __align__(16) float g_encW[512 * 4096];       // Wc @ enc^T : [j][b*128+s]
__device__ __align__(16) float g_sc[Bn][Sn];             // softmax weights per step
__device__ __align__(16) float g_attT[Hn * Hn];
__device__ __nv_bfloat16 g_Ahi[Bn * Tn * En];
__device__ __nv_bfloat16 g_Alo[Bn * Tn * En];
__device__ __nv_bfloat16 g_Bhi[(size_t)Vn * En];
__device__ __nv_bfloat16 g_Blo[(size_t)Vn * En];
__device__ unsigned g_count;
__device__ volatile unsigned g_gen;

// ---------------- small helpers ----------------
__device__ __forceinline__ uint32_t s2u(const void* p)
{
    uint32_t a;
    asm("{ .reg .u64 t; cvta.to.shared.u64 t, %1; cvt.u32.u64 %0, t; }" : "=r"(a) : "l"(p));
    return a;
}
__device__ __forceinline__ void cp16(uint32_t s, const void* g)
{
    asm volatile("cp.async.cg.shared.global [%0], [%1], 16;" :: "r"(s), "l"(g) : "memory");
}
__device__ __forceinline__ float sigm(float x) { return 1.f / (1.f + __expf(-x)); }

__device__ __forceinline__ unsigned long long pack2(float x)
{ unsigned long long r; asm("mov.b64 %0, {%1, %1};" : "=l"(r) : "f"(x)); return r; }
__device__ __forceinline__ unsigned long long pack2f(float x, float y)
{ unsigned long long r; asm("mov.b64 %0, {%1, %2};" : "=l"(r) : "f"(x), "f"(y)); return r; }
__device__ __forceinline__ void ffma2(unsigned long long& d, unsigned long long a, unsigned long long b)
{ asm("fma.rn.f32x2 %0, %1, %2, %0;" : "+l"(d) : "l"(a), "l"(b)); }
__device__ __forceinline__ float2 unpack2(unsigned long long v)
{ float2 r; asm("mov.b64 {%0, %1}, %2;" : "=f"(r.x), "=f"(r.y) : "l"(v)); return r; }

__device__ __forceinline__ void split_bf16(float v, __nv_bfloat16& h, __nv_bfloat16& l)
{
    h = __float2bfloat16(v);
    l = __float2bfloat16(v - __bfloat162float(h));
}

// ---------------- grid barrier (128 CTAs co-resident) ----------------
__device__ __forceinline__ void gbar()
{
    __threadfence();
    __syncthreads();
    if (threadIdx.x == 0) {
        unsigned g = g_gen;
        unsigned a = atomicAdd(&g_count, 1u);
        if (a == NCTA - 1u) {
            g_count = 0u;
            __threadfence();
            g_gen = g + 1u;
        } else {
            while (g_gen == g) { }
        }
    }
    __syncthreads();
    __threadfence();
}

// dynamic smem: packed f32x2 weights [warp][kpair][row]
static constexpr int WA2 = 8192, WB2 = 8192, WE2 = 1024;   // wE: 16 w * 16 kp * 4 r
static constexpr int DSMEM = (WA2 + WB2 + WE2) * 8;        // 139264 B

// ---------------- embed gather ----------------
__global__ void __launch_bounds__(256)
gather_x(const int* __restrict__ tokens, const float* __restrict__ embed)
{
    int p = blockIdx.x * 8 + (threadIdx.x >> 5);
    int lane = threadIdx.x & 31;
    int t = p >> 5, b = p & 31;
    int tok = __ldg(tokens + b * Tn + t);
    const float4* er = (const float4*)(embed + (size_t)tok * En);
    float4* dr = (float4*)g_x[t * Bn + b];
#pragma unroll
    for (int i = 0; i < 4; i++)
        dr[i * 32 + lane] = __ldg(er + i * 32 + lane);
}

// warp-sliced matvec: NR rows x (KPC*2) k, act[k][32] global, weights smem f32x2
template<int NR, int KPC>
__device__ __forceinline__ void mv16k(const float2* __restrict__ wslice,
                                      const float* __restrict__ act,
                                      int lane, float* __restrict__ red)
{
    unsigned long long acc[NR];
#pragma unroll
    for (int r = 0; r < NR; r++) acc[r] = 0ull;
#pragma unroll 8
    for (int kp = 0; kp < KPC; kp++) {
        float a0 = __ldca(act + kp * 64 + lane);
        float a1 = __ldca(act + kp * 64 + 32 + lane);
        unsigned long long av = pack2f(a0, a1);
        const ulonglong2* wrow = (const ulonglong2*)(wslice + kp * NR);
#pragma unroll
        for (int rp = 0; rp < NR / 2; rp++) {
            ulonglong2 wv = wrow[rp];
            ffma2(acc[rp * 2], wv.x, av);
            ffma2(acc[rp * 2 + 1], wv.y, av);
        }
    }
#pragma unroll
    for (int r = 0; r < NR; r++) {
        float2 v = unpack2(acc[r]);
        red[r * 32 + lane] = v.x + v.y;
    }
}

// ---------------- persistent recurrence (512 threads: 16 warps) ----------------
__global__ void __launch_bounds__(NTHR, 1)
recurrent_kernel(const float* __restrict__ enc,
                 const int* __restrict__ mask,
                 const float* __restrict__ w_ih0, const float* __restrict__ w_hh0,
                 const float* __restrict__ b_ih0, const float* __restrict__ b_hh0,
                 const float* __restrict__ w_ih1, const float* __restrict__ w_hh1,
                 const float* __restrict__ b_ih1, const float* __restrict__ b_hh1,
                 const float* __restrict__ attn_out_w)
{
    extern __shared__ __align__(16) float2 wsm2[];
    float2* wA = wsm2;
    float2* wB = wA + WA2;
    float2* wE = wB + WB2;

    const int tid = threadIdx.x, cta = blockIdx.x;
    const int warp = tid >> 5, lane = tid & 31;
    const int gtid = cta * NTHR + tid;

    __shared__ __align__(16) float sAred[16][16][32];
    __shared__ __align__(16) float gs[16][32];
    __shared__ __align__(16) float s_q[512];
    __shared__ __align__(16) float s_scall[32][128];
    __shared__ float s_sc[128];
    __shared__ float s_att[4][32];
    __shared__ float s_red[32];

    for (int i = gtid; i < Hn * Bn; i += NCTA * NTHR) {
        (&g_feedT[0][0])[i] = 0.f;
        (&g_h0T[0][0][0])[i] = 0.f; (&g_h0T[1][0][0])[i] = 0.f;
        (&g_h1T[0][0][0])[i] = 0.f; (&g_h1T[1][0][0])[i] = 0.f;
    }

    // stage packed weights
    for (int i = tid; i < WA2; i += NTHR) {
        int w = i >> 9, kp = (i >> 4) & 31, r = i & 15;
        int grow = (r & 3) * 512 + cta * 4 + (r >> 2);
        int k = w * 64 + kp * 2;
        float2 v;
        if (k < 512) {
            const float* p = w_ih0 + (size_t)grow * 1024 + 512 + k;
            v = make_float2(__ldg(p), __ldg(p + 1));
        } else {
            const float* p = w_hh0 + (size_t)grow * 512 + (k - 512);
            v = make_float2(__ldg(p), __ldg(p + 1));
        }
        wA[i] = v;
    }
    for (int i = tid; i < WB2; i += NTHR) {
        int w = i >> 9, kp = (i >> 4) & 31, r = i & 15;
        int grow = (r & 3) * 512 + cta * 4 + (r >> 2);
        int k = w * 64 + kp * 2;
        float2 v;
        if (k < 512) {
            const float* p = w_ih1 + (size_t)grow * 512 + k;
            v = make_float2(__ldg(p), __ldg(p + 1));
        } else {
            const float* p = w_hh1 + (size_t)grow * 512 + (k - 512);
            v = make_float2(__ldg(p), __ldg(p + 1));
        }
        wB[i] = v;
    }
    // wE: Wh half of attn_out_w (cols 512..1023), 4 rows, 512 K over 16 warps
    for (int i = tid; i < WE2; i += NTHR) {
        int w = i >> 6, kp = (i >> 2) & 15, r = i & 3;
        int k = w * 32 + kp * 2;
        const float* p = attn_out_w + (size_t)(cta * 4 + r) * 1024 + 512 + k;
        wE[i] = make_float2(__ldg(p), __ldg(p + 1));
    }
    gbar();

    const int db = cta >> 2, dp = cta & 3;

    float c0r = 0.f, c1r = 0.f;
    float biA[4], biB[4];
    if (tid < 128) {
        int jj = tid >> 5, ju = cta * 4 + jj;
#pragma unroll
        for (int rr = 0; rr < 4; rr++) {
            biA[rr] = __ldg(b_ih0 + ju + 512 * rr) + __ldg(b_hh0 + ju + 512 * rr);
            biB[rr] = __ldg(b_ih1 + ju + 512 * rr) + __ldg(b_hh1 + ju + 512 * rr);
        }
    }

    for (int t = 0; t < Tn; t++) {
        const int cur = t & 1, prv = cur ^ 1;

        // ---------- Phase A: layer-0 gates (feed512|h0prv512; x-part precomputed) ----------
        {
            float xwv[4];
            if (tid < 128) {
                int b = tid & 31, jj = tid >> 5;
                const float* xwrow = g_xw + (size_t)(t * Bn + b) * 2048 + cta * 4 + jj;
#pragma unroll
                for (int rr = 0; rr < 4; rr++) xwv[rr] = __ldcg(xwrow + 512 * rr);
            }
            const float* act = (warp < 8) ? &g_feedT[warp * 64][0]
                                          : &g_h0T[prv][(warp - 8) * 64][0];
            mv16k<16, 32>(wA + warp * 32 * 16, act, lane, &sAred[warp][0][0]);
            __syncthreads();
            {
                int row = tid >> 5, b = tid & 31;
                float s = 0.f;
#pragma unroll
                for (int w = 0; w < 16; w++) s += sAred[w][row][b];
                gs[row][b] = s;
            }
            __syncthreads();
            if (tid < 128) {
                int b = tid & 31, jj = tid >> 5;
                float gi = gs[jj * 4 + 0][b] + biA[0] + xwv[0];
                float gf = gs[jj * 4 + 1][b] + biA[1] + xwv[1];
                float gg = gs[jj * 4 + 2][b] + biA[2] + xwv[2];
                float go = gs[jj * 4 + 3][b] + biA[3] + xwv[3];
                c0r = sigm(gf) * c0r + sigm(gi) * tanhf(gg);
                g_h0T[cur][cta * 4 + jj][b] = sigm(go) * tanhf(c0r);
            }
        }
        gbar();

        // ---------- Phase B: layer-1 gates (h0cur512|h1prv512) ----------
        {
            const float* act = (warp < 8) ? &g_h0T[cur][warp * 64][0]
                                          : &g_h1T[prv][(warp - 8) * 64][0];
            mv16k<16, 32>(wB + warp * 32 * 16, act, lane, &sAred[warp][0][0]);
            __syncthreads();
            {
                int row = tid >> 5, b = tid & 31;
                float s = 0.f;
#pragma unroll
                for (int w = 0; w < 16; w++) s += sAred[w][row][b];
                gs[row][b] = s;
            }
            __syncthreads();
            if (tid < 128) {
                int b = tid & 31, jj = tid >> 5;
                float gi = gs[jj * 4 + 0][b] + biB[0];
                float gf = gs[jj * 4 + 1][b] + biB[1];
                float gg = gs[jj * 4 + 2][b] + biB[2];
                float go = gs[jj * 4 + 3][b] + biB[3];
                c1r = sigm(gf) * c1r + sigm(gi) * tanhf(gg);
                g_h1T[cur][cta * 4 + jj][b] = sigm(go) * tanhf(c1r);
            }
        }
        gbar();

        // ---------- Phase S': scores+softmax (batch db) + Wh@h1 partials ----------
        {
            const int b = db;
            s_q[tid] = __ldca(&g_h1T[cur][tid][b]);
            __syncthreads();
#pragma unroll
            for (int i = 0; i < 8; i++) {
                int sp = warp * 8 + i;
                const float4* er = (const float4*)(g_encq[(size_t)b * Sn + sp]);
                const float4* qr = (const float4*)s_q;
                float acc = 0.f;
#pragma unroll
                for (int c4 = 0; c4 < 4; c4++) {
                    float4 e = __ldca(er + c4 * 32 + lane);
                    float4 q4 = qr[c4 * 32 + lane];
                    acc += e.x * q4.x + e.y * q4.y + e.z * q4.z + e.w * q4.w;
                }
#pragma unroll
                for (int o = 16; o; o >>= 1) acc += __shfl_xor_sync(~0u, acc, o);
                if (lane == 0)
                    s_sc[sp] = (__ldg(mask + b * Sn + sp) == 0) ? NEGV : acc;
            }
            __syncthreads();
            float mv = (tid < 128) ? s_sc[tid] : -3e38f;
#pragma unroll
            for (int o = 16; o; o >>= 1) mv = fmaxf(mv, __shfl_xor_sync(~0u, mv, o));
            if (tid < 128 && lane == 0) s_red[warp] = mv;
            __syncthreads();
            if (tid == 0) {
                float m = s_red[0];
                for (int w = 1; w < 4; w++) m = fmaxf(m, s_red[w]);
                s_red[16] = m;
            }
            __syncthreads();
            float ev = 0.f;
            if (tid < 128) ev = __expf(s_sc[tid] - s_red[16]);
            float sv = ev;
#pragma unroll
            for (int o = 16; o; o >>= 1) sv += __shfl_xor_sync(~0u, sv, o);
            if (tid < 128 && lane == 0) s_red[warp] = sv;
            __syncthreads();
            if (tid == 0) {
                float s = 0.f;
                for (int w = 0; w < 4; w++) s += s_red[w];
                s_red[17] = 1.f / s;
            }
            __syncthreads();
            if (tid < 128) {
                float pval = ev * s_red[17];
                if (dp == 0) g_sc[b][tid] = pval;
            }
            // Wh @ h1 partials (persist in sAred across the barrier)
            mv16k<4, 16>(wE + warp * 16 * 4, &g_h1T[cur][warp * 32][0], lane,
                         &sAred[warp][0][0]);
        }
        gbar();

        // ---------- Phase E'': attn dot (encW @ p) + combine -> feed ----------
        {
            for (int i = tid; i < 32 * 128; i += NTHR)
                (&s_scall[0][0])[i] = __ldca(&g_sc[0][0] + i);
            __syncthreads();
            float4 ew[8];
#pragma unroll
            for (int pp = 0; pp < 8; pp++) {
                int p = warp * 8 + pp;
                int r = p >> 5, b = p & 31;
                ew[pp] = __ldg((const float4*)(g_encW + (size_t)(cta * 4 + r) * 4096
                                               + b * 128) + lane);
            }
#pragma unroll
            for (int pp = 0; pp < 8; pp++) {
                int p = warp * 8 + pp;
                int r = p >> 5, b = p & 31;
                float4 pv = *((const float4*)&s_scall[b][0] + lane);
                float acc = ew[pp].x * pv.x + ew[pp].y * pv.y
                          + ew[pp].z * pv.z + ew[pp].w * pv.w;
#pragma unroll
                for (int o = 16; o; o >>= 1) acc += __shfl_xor_sync(~0u, acc, o);
                if (lane == 0) s_att[r][b] = acc;
            }
            __syncthreads();
            if (tid < 128) {
                int b = tid & 31, row = tid >> 5;
                float s = s_att[row][b];
#pragma unroll
                for (int w = 0; w < 16; w++) s += sAred[w][row][b];
                float f = tanhf(s);
                g_feedT[cta * 4 + row][b] = f;
                g_dec[b * Tn + t][cta * 4 + row] = f;
            }
        }
        gbar();
    }
}

// ---------------- 512x512 transpose ----------------
__global__ void __launch_bounds__(256)
trans512(const float* __restrict__ src, float* __restrict__ dst)
{
    __shared__ float tile[32][33];
    int bx = blockIdx.x * 32, by = blockIdx.y * 32;
    int tx = threadIdx.x & 31, ty = threadIdx.x >> 5;
#pragma unroll
    for (int i = 0; i < 4; i++)
        tile[ty + i * 8][tx] = __ldg(src + (size_t)(by + ty + i * 8) * 512 + bx + tx);
    __syncthreads();
#pragma unroll
    for (int i = 0; i < 4; i++)
        dst[(size_t)(bx + ty + i * 8) * 512 + by + tx] = tile[tx][ty + i * 8];
}

// ---------------- SIMT f32x2 gemm: C = A @ W^T, fp32; row strides lda/ldw ----------------
__global__ void __launch_bounds__(256)
gemm_nt(const float* __restrict__ A, const float* __restrict__ W,
        const float* __restrict__ bias, float* __restrict__ C,
        int M, int N, int K, int ldw, int lda)
{
    __shared__ __align__(16) float As[16][128];
    __shared__ __align__(16) float Ws[16][128];
    const int m0 = blockIdx.y * 128, n0 = blockIdx.x * 128;
    const int tid = threadIdx.x;
    const int tx = tid & 15, ty = tid >> 4;
    const int lrow = tid >> 1, lcol = (tid & 1) * 8;

    unsigned long long acc2[8][4];
#pragma unroll
    for (int i = 0; i < 8; i++)
#pragma unroll
        for (int jj = 0; jj < 4; jj++) acc2[i][jj] = 0ull;

    const float* Aload = A + (size_t)(m0 + lrow) * lda + lcol;
    const float* Wload = W + (size_t)(n0 + lrow) * ldw + lcol;

    for (int k0 = 0; k0 < K; k0 += 16) {
        float4 a0 = __ldg((const float4*)(Aload + k0));
        float4 a1 = __ldg((const float4*)(Aload + k0 + 4));
        float4 w0 = __ldg((const float4*)(Wload + k0));
        float4 w1 = __ldg((const float4*)(Wload + k0 + 4));
        __syncthreads();
        As[lcol + 0][lrow] = a0.x; As[lcol + 1][lrow] = a0.y;
        As[lcol + 2][lrow] = a0.z; As[lcol + 3][lrow] = a0.w;
        As[lcol + 4][lrow] = a1.x; As[lcol + 5][lrow] = a1.y;
        As[lcol + 6][lrow] = a1.z; As[lcol + 7][lrow] = a1.w;
        Ws[lcol + 0][lrow] = w0.x; Ws[lcol + 1][lrow] = w0.y;
        Ws[lcol + 2][lrow] = w0.z; Ws[lcol + 3][lrow] = w0.w;
        Ws[lcol + 4][lrow] = w1.x; Ws[lcol + 5][lrow] = w1.y;
        Ws[lcol + 6][lrow] = w1.z; Ws[lcol + 7][lrow] = w1.w;
        __syncthreads();
#pragma unroll
        for (int kk = 0; kk < 16; kk++) {
            float4 av0 = *(const float4*)&As[kk][ty * 8];
            float4 av1 = *(const float4*)&As[kk][ty * 8 + 4];
            const ulonglong2* wp = (const ulonglong2*)&Ws[kk][tx * 8];
            ulonglong2 b01 = wp[0], b23 = wp[1];
            float a8[8] = {av0.x, av0.y, av0.z, av0.w, av1.x, av1.y, av1.z, av1.w};
#pragma unroll
            for (int i = 0; i < 8; i++) {
                unsigned long long a2 = pack2(a8[i]);
                ffma2(acc2[i][0], a2, b01.x);
                ffma2(acc2[i][1], a2, b01.y);
                ffma2(acc2[i][2], a2, b23.x);
                ffma2(acc2[i][3], a2, b23.y);
            }
        }
    }
#pragma unroll
    for (int i = 0; i < 8; i++) {
        float* Crow = C + (size_t)(m0 + ty * 8 + i) * N + n0 + tx * 8;
#pragma unroll
        for (int jj = 0; jj < 4; jj++) {
            float2 v = unpack2(acc2[i][jj]);
            if (bias) {
                v.x += __ldg(bias + n0 + tx * 8 + 2 * jj);
                v.y += __ldg(bias + n0 + tx * 8 + 2 * jj + 1);
            }
            *(float2*)(Crow + 2 * jj) = v;
        }
    }
}

// ---------------- SIMT f32x2 gemm (out_proj) -> bf16 hi/lo ----------------
__global__ void __launch_bounds__(256)
gemm_nt_split(const float* __restrict__ A, const float* __restrict__ W,
              const float* __restrict__ bias,
              __nv_bfloat16* __restrict__ Chi, __nv_bfloat16* __restrict__ Clo,
              int M, int N, int K)
{
    __shared__ __align__(16) float As[16][128];
    __shared__ __align__(16) float Ws[16][128];
    const int m0 = blockIdx.y * 128, n0 = blockIdx.x * 128;
    const int tid = threadIdx.x;
    const int tx = tid & 15, ty = tid >> 4;
    const int lrow = tid >> 1, lcol = (tid & 1) * 8;

    unsigned long long acc2[8][4];
#pragma unroll
    for (int i = 0; i < 8; i++)
#pragma unroll
        for (int jj = 0; jj < 4; jj++) acc2[i][jj] = 0ull;

    const float* Aload = A + (size_t)(m0 + lrow) * K + lcol;
    const float* Wload = W + (size_t)(n0 + lrow) * K + lcol;

    for (int k0 = 0; k0 < K; k0 += 16) {
        float4 a0 = __ldg((const float4*)(Aload + k0));
        float4 a1 = __ldg((const float4*)(Aload + k0 + 4));
        float4 w0 = __ldg((const float4*)(Wload + k0));
        float4 w1 = __ldg((const float4*)(Wload + k0 + 4));
        __syncthreads();
        As[lcol + 0][lrow] = a0.x; As[lcol + 1][lrow] = a0.y;
        As[lcol + 2][lrow] = a0.z; As[lcol + 3][lrow] = a0.w;
        As[lcol + 4][lrow] = a1.x; As[lcol + 5][lrow] = a1.y;
        As[lcol + 6][lrow] = a1.z; As[lcol + 7][lrow] = a1.w;
        Ws[lcol + 0][lrow] = w0.x; Ws[lcol + 1][lrow] = w0.y;
        Ws[lcol + 2][lrow] = w0.z; Ws[lcol + 3][lrow] = w0.w;
        Ws[lcol + 4][lrow] = w1.x; Ws[lcol + 5][lrow] = w1.y;
        Ws[lcol + 6][lrow] = w1.z; Ws[lcol + 7][lrow] = w1.w;
        __syncthreads();
#pragma unroll
        for (int kk = 0; kk < 16; kk++) {
            float4 av0 = *(const float4*)&As[kk][ty * 8];
            float4 av1 = *(const float4*)&As[kk][ty * 8 + 4];
            const ulonglong2* wp = (const ulonglong2*)&Ws[kk][tx * 8];
            ulonglong2 b01 = wp[0], b23 = wp[1];
            float a8[8] = {av0.x, av0.y, av0.z, av0.w, av1.x, av1.y, av1.z, av1.w};
#pragma unroll
            for (int i = 0; i < 8; i++) {
                unsigned long long a2 = pack2(a8[i]);
                ffma2(acc2[i][0], a2, b01.x);
                ffma2(acc2[i][1], a2, b01.y);
                ffma2(acc2[i][2], a2, b23.x);
                ffma2(acc2[i][3], a2, b23.y);
            }
        }
    }
#pragma unroll
    for (int i = 0; i < 8; i++) {
        size_t rowoff = (size_t)(m0 + ty * 8 + i) * N + n0 + tx * 8;
        unsigned short tmph[8], tmpl[8];
#pragma unroll
        for (int jj = 0; jj < 4; jj++) {
            float2 v = unpack2(acc2[i][jj]);
            v.x += __ldg(bias + n0 + tx * 8 + 2 * jj);
            v.y += __ldg(bias + n0 + tx * 8 + 2 * jj + 1);
            __nv_bfloat16 h0, l0, h1, l1;
            split_bf16(v.x, h0, l0);
            split_bf16(v.y, h1, l1);
            tmph[2 * jj] = __bfloat16_as_ushort(h0); tmph[2 * jj + 1] = __bfloat16_as_ushort(h1);
            tmpl[2 * jj] = __bfloat16_as_ushort(l0); tmpl[2 * jj + 1] = __bfloat16_as_ushort(l1);
        }
        uint2 H, L, H2, L2;
        H.x = (uint32_t)tmph[0] | ((uint32_t)tmph[1] << 16);
        H.y = (uint32_t)tmph[2] | ((uint32_t)tmph[3] << 16);
        L.x = (uint32_t)tmpl[0] | ((uint32_t)tmpl[1] << 16);
        L.y = (uint32_t)tmpl[2] | ((uint32_t)tmpl[3] << 16);
        H2.x = (uint32_t)tmph[4] | ((uint32_t)tmph[5] << 16);
        H2.y = (uint32_t)tmph[6] | ((uint32_t)tmph[7] << 16);
        L2.x = (uint32_t)tmpl[4] | ((uint32_t)tmpl[5] << 16);
        L2.y = (uint32_t)tmpl[6] | ((uint32_t)tmpl[7] << 16);
        *(uint2*)(Chi + rowoff) = H;  *(uint2*)(Chi + rowoff + 4) = H2;
        *(uint2*)(Clo + rowoff) = L;  *(uint2*)(Clo + rowoff + 4) = L2;
    }
}

// ---------------- fp32 -> bf16 hi/lo split (embed) ----------------
__global__ void __launch_bounds__(256)
conv_split(const float4* __restrict__ src, uint2* __restrict__ hi, uint2* __restrict__ lo)
{
    int i = blockIdx.x * 256 + threadIdx.x;
    float4 v = __ldg(src + i);
    __nv_bfloat16 h0, l0, h1, l1, h2, l2, h3, l3;
    split_bf16(v.x, h0, l0); split_bf16(v.y, h1, l1);
    split_bf16(v.z, h2, l2); split_bf16(v.w, h3, l3);
    uint2 H, L;
    H.x = (uint32_t)__bfloat16_as_ushort(h0) | ((uint32_t)__bfloat16_as_ushort(h1) << 16);
    H.y = (uint32_t)__bfloat16_as_ushort(h2) | ((uint32_t)__bfloat16_as_ushort(h3) << 16);
    L.x = (uint32_t)__bfloat16_as_ushort(l0) | ((uint32_t)__bfloat16_as_ushort(l1) << 16);
    L.y = (uint32_t)__bfloat16_as_ushort(l2) | ((uint32_t)__bfloat16_as_ushort(l3) << 16);
    hi[i] = H; lo[i] = L;
}

// ---------------- mma.sync bf16 3-pass GEMM: C = A @ B^T ----------------
static constexpr int KC = 32;
static constexpr int NCHUNK = En / KC;
static constexpr int ROWB = 80;
static constexpr int MATB = 128 * ROWB;
static constexpr int STAGEB = 4 * MATB;
static constexpr int GSMEM2 = 2 * STAGEB;

__device__ __forceinline__ void ldmA(uint32_t* r, uint32_t addr)
{
    asm volatile("ldmatrix.sync.aligned.m8n8.x4.shared.b16 {%0,%1,%2,%3}, [%4];"
                 : "=r"(r[0]), "=r"(r[1]), "=r"(r[2]), "=r"(r[3]) : "r"(addr));
}
__device__ __forceinline__ void ldmB(uint32_t* r, uint32_t addr)
{
    asm volatile("ldmatrix.sync.aligned.m8n8.x2.shared.b16 {%0,%1}, [%2];"
                 : "=r"(r[0]), "=r"(r[1]) : "r"(addr));
}
__device__ __forceinline__ void mma16816(float* d, const uint32_t* a, const uint32_t* b)
{
    asm volatile("mma.sync.aligned.m16n8k16.row.col.f32.bf16.bf16.f32 "
                 "{%0,%1,%2,%3}, {%4,%5,%6,%7}, {%8,%9}, {%0,%1,%2,%3};"
                 : "+f"(d[0]), "+f"(d[1]), "+f"(d[2]), "+f"(d[3])
                 : "r"(a[0]), "r"(a[1]), "r"(a[2]), "r"(a[3]), "r"(b[0]), "r"(b[1]));
}

__global__ void __launch_bounds__(256, 2)
gemm_bf16(const __nv_bfloat16* __restrict__ Ahi, const __nv_bfloat16* __restrict__ Alo,
          const __nv_bfloat16* __restrict__ Bhi, const __nv_bfloat16* __restrict__ Blo,
          float* __restrict__ C, int N, int K)
{
    extern __shared__ char smem[];
    const uint32_t su = s2u(smem);
    const int tid = threadIdx.x, wid = tid >> 5, lane = tid & 31;
    const int m0 = blockIdx.y * 128, n0 = blockIdx.x * 128;
    const int wm = wid & 1, wn = wid >> 1;

    auto load_stage = [&](int chunk) {
        const uint32_t sb = su + (chunk & 1) * STAGEB;
#pragma unroll
        for (int r8 = 0; r8 < 8; r8++) {
            int ci = tid + r8 * 256;
            int mat = ci >> 9, rem = ci & 511;
            int row = rem >> 2, seg = rem & 3;
            const __nv_bfloat16* g;
            if (mat == 0)      g = Ahi + (size_t)(m0 + row) * K + chunk * KC + seg * 8;
            else if (mat == 1) g = Alo + (size_t)(m0 + row) * K + chunk * KC + seg * 8;
            else if (mat == 2) g = Bhi + (size_t)(n0 + row) * K + chunk * KC + seg * 8;
            else               g = Blo + (size_t)(n0 + row) * K + chunk * KC + seg * 8;
            cp16(sb + mat * MATB + row * ROWB + seg * 16, g);
        }
        asm volatile("cp.async.commit_group;" ::: "memory");
    };

    float acc[4][4][4];
#pragma unroll
    for (int i = 0; i < 4; i++)
#pragma unroll
        for (int jj = 0; jj < 4; jj++)
#pragma unroll
            for (int k = 0; k < 4; k++) acc[i][jj][k] = 0.f;

    load_stage(0);
    load_stage(1);

    for (int c = 0; c < NCHUNK; c++) {
        if (c < NCHUNK - 1) asm volatile("cp.async.wait_group 1;" ::: "memory");
        else                asm volatile("cp.async.wait_group 0;" ::: "memory");
        __syncthreads();
        const uint32_t sb = su + (c & 1) * STAGEB;
        const uint32_t aHiB = sb,            aLoB = sb + MATB;
        const uint32_t bHiB = sb + 2 * MATB, bLoB = sb + 3 * MATB;
#pragma unroll
        for (int ks = 0; ks < 2; ks++) {
            const uint32_t aoff = (uint32_t)((wm * 64 + (lane & 15)) * ROWB
                                             + (ks * 16 + (lane >> 4) * 8) * 2);
            const int l = lane & 15;
            const uint32_t boff = (uint32_t)((wn * 32 + (l & 7)) * ROWB
                                             + (ks * 16 + (l >> 3) * 8) * 2);
            uint32_t ah[4][4], al[4][4], bh[4][2], bl[4][2];
#pragma unroll
            for (int mi = 0; mi < 4; mi++) {
                ldmA(ah[mi], aHiB + aoff + mi * 16 * ROWB);
                ldmA(al[mi], aLoB + aoff + mi * 16 * ROWB);
            }
#pragma unroll
            for (int ni = 0; ni < 4; ni++) {
                ldmB(bh[ni], bHiB + boff + ni * 8 * ROWB);
                ldmB(bl[ni], bLoB + boff + ni * 8 * ROWB);
            }
#pragma unroll
            for (int mi = 0; mi < 4; mi++)
#pragma unroll
                for (int ni = 0; ni < 4; ni++) {
                    mma16816(acc[mi][ni], ah[mi], bh[ni]);
                    mma16816(acc[mi][ni], ah[mi], bl[ni]);
                    mma16816(acc[mi][ni], al[mi], bh[ni]);
                }
        }
        __syncthreads();
        if (c + 2 < NCHUNK) load_stage(c + 2);
    }

    const int mbase = m0 + wm * 64 + (lane >> 2);
    const int nbase = n0 + wn * 32 + (lane & 3) * 2;
#pragma unroll
    for (int mi = 0; mi < 4; mi++)
#pragma unroll
        for (int ni = 0; ni < 4; ni++) {
            float* p0 = C + (size_t)(mbase + mi * 16) * N + nbase + ni * 8;
            float* p1 = C + (size_t)(mbase + mi * 16 + 8) * N + nbase + ni * 8;
            *(float2*)p0 = make_float2(acc[mi][ni][0], acc[mi][ni][1]);
            *(float2*)p1 = make_float2(acc[mi][ni][2], acc[mi][ni][3]);
        }
}

extern "C" void kernel_launch(void* const* d_in, const int* in_sizes, int n_in,
                              void* d_out, int out_size)
{
    const int*   tokens     = (const int*)d_in[0];
    const float* enc        = (const float*)d_in[1];
    const int*   mask       = (const int*)d_in[2];
    const float* embed      = (const float*)d_in[3];
    const float* w_ih0      = (const float*)d_in[4];
    const float* w_hh0      = (const float*)d_in[5];
    const float* b_ih0      = (const float*)d_in[6];
    const float* b_hh0      = (const float*)d_in[7];
    const float* w_ih1      = (const float*)d_in[8];
    const float* w_hh1      = (const float*)d_in[9];
    const float* b_ih1      = (const float*)d_in[10];
    const float* b_hh1      = (const float*)d_in[11];
    const float* attn_in_w  = (const float*)d_in[12];
    const float* attn_out_w = (const float*)d_in[13];
    const float* out_proj_w = (const float*)d_in[14];
    const float* out_proj_b = (const float*)d_in[15];
    float* out = (float*)d_out;

    float *dec, *encq, *encW, *attT, *xrow, *xw;
    __nv_bfloat16 *Ahi, *Alo, *Bhi, *Blo;
    cudaGetSymbolAddress((void**)&dec, g_dec);
    cudaGetSymbolAddress((void**)&encq, g_encq);
    cudaGetSymbolAddress((void**)&encW, g_encW);
    cudaGetSymbolAddress((void**)&attT, g_attT);
    cudaGetSymbolAddress((void**)&xrow, g_x);
    cudaGetSymbolAddress((void**)&xw, g_xw);
    cudaGetSymbolAddress((void**)&Ahi, g_Ahi);
    cudaGetSymbolAddress((void**)&Alo, g_Alo);
    cudaGetSymbolAddress((void**)&Bhi, g_Bhi);
    cudaGetSymbolAddress((void**)&Blo, g_Blo);

    cudaFuncSetAttribute(gemm_bf16, cudaFuncAttributeMaxDynamicSharedMemorySize, GSMEM2);
    cudaFuncSetAttribute(recurrent_kernel, cudaFuncAttributeMaxDynamicSharedMemorySize, DSMEM);

    static cudaStream_t s2 = nullptr, s3 = nullptr;
    static cudaEvent_t evA = nullptr, evB = nullptr, evX = nullptr;
    if (!s2) {
        cudaStreamCreateWithFlags(&s2, cudaStreamNonBlocking);
        cudaStreamCreateWithFlags(&s3, cudaStreamNonBlocking);
        cudaEventCreateWithFlags(&evA, cudaEventDisableTiming);
        cudaEventCreateWithFlags(&evB, cudaEventDisableTiming);
        cudaEventCreateWithFlags(&evX, cudaEventDisableTiming);
    }

    cudaEventRecord(evA, 0);
    cudaStreamWaitEvent(s2, evA, 0);
    cudaStreamWaitEvent(s3, evA, 0);

    // s2: embed hi/lo conversion (overlaps pre-GEMMs + recurrence; proven harmless)
    conv_split<<<Vn * En / 1024, 256, 0, s2>>>((const float4*)embed, (uint2*)Bhi, (uint2*)Blo);
    cudaEventRecord(evB, s2);

    // s3: x-side chain (xw) + encW = Wc @ enc^T (both pre-recurrence)
    gather_x<<<256, 256, 0, s3>>>(tokens, embed);
    gemm_nt<<<dim3(2048 / 128, (Bn * Tn) / 128), 256, 0, s3>>>(xrow, w_ih0, nullptr, xw,
                                                               Bn * Tn, 2048, 512, 1024, 512);
    gemm_nt<<<dim3(4096 / 128, 512 / 128), 256, 0, s3>>>(attn_out_w, enc, nullptr, encW,
                                                         512, 4096, 512, 512, 1024);
    cudaEventRecord(evX, s3);

    // stream0: attn pre + recurrence + out_proj + vocab GEMM
    trans512<<<dim3(16, 16), 256>>>(attn_in_w, attT);
    gemm_nt<<<dim3(Hn / 128, (Bn * Sn) / 128), 256>>>(enc, attT, nullptr, encq,
                                                      Bn * Sn, Hn, Hn, Hn, Hn);
    cudaStreamWaitEvent(0, evX, 0);
    recurrent_kernel<<<NCTA, NTHR, DSMEM>>>(enc, mask,
                                            w_ih0, w_hh0, b_ih0, b_hh0,
                                            w_ih1, w_hh1, b_ih1, b_hh1,
                                            attn_out_w);
    gemm_nt_split<<<dim3(En / 128, (Bn * Tn) / 128), 256>>>(dec, out_proj_w, out_proj_b,
                                                            Ahi, Alo, Bn * Tn, En, Hn);
    cudaStreamWaitEvent(0, evB, 0);
    gemm_bf16<<<dim3(Vn / 128, (Bn * Tn) / 128), 256, GSMEM2>>>(Ahi, Alo, Bhi, Blo, out, Vn, En);
}